// round 6
// baseline (speedup 1.0000x reference)
#include <cuda_runtime.h>
#include <stdint.h>

#define N_NODES   100000
#define N_EDGES   25000
#define NNZ_MAX   2000000
#define HO        64
#define IN_CH     64

#define TILE      4096
#define TE        ((N_EDGES + TILE - 1) / TILE)   // 7
#define TV        ((N_NODES + TILE - 1) / TILE)   // 25

// ---------------- scratch (device globals; no allocation) ----------------
__device__ __align__(16) float g_Xe[N_EDGES * HO];
__device__ int   g_ecnt[N_EDGES];
__device__ int   g_vcnt[N_NODES];
__device__ float g_att[N_NODES];
__device__ int   g_erow[N_EDGES + 1];
__device__ int   g_vrow[N_NODES + 1];
__device__ int   g_eoff[N_EDGES];
__device__ int   g_voff[N_NODES];
__device__ int   g_evid[NNZ_MAX];
__device__ int   g_veid[NNZ_MAX];
__device__ int   g_epart[TE];
__device__ int   g_vpart[TV];

// ---------------- kernel A: zero counters ----------------
__global__ void zero_kernel()
{
    int idx = blockIdx.x * blockDim.x + threadIdx.x;
    if (idx < N_EDGES) g_ecnt[idx] = 0;
    if (idx < N_NODES) { g_vcnt[idx] = 0; g_att[idx] = 0.f; }
}

// ---------------- kernel B: fused GEMM (Xp = X@W -> out) + histograms -------
__global__ void gemm_hist_kernel(const float* __restrict__ X,
                                 const float* __restrict__ W,
                                 float* __restrict__ out,
                                 const float* __restrict__ homo,
                                 const int* __restrict__ vertex,
                                 const int* __restrict__ edges,
                                 int n, int nnz, int gemm_blocks)
{
    __shared__ float sW[64 * 64];
    __shared__ float sX[64 * 65];

    if (blockIdx.x < gemm_blocks) {
        const int t  = threadIdx.x;
        const int r0 = blockIdx.x * 64;

        #pragma unroll
        for (int idx = t; idx < 64 * 64; idx += 256) sW[idx] = W[idx];
        #pragma unroll
        for (int idx = t; idx < 64 * 64; idx += 256) {
            int r = idx >> 6, k = idx & 63;
            int gr = r0 + r;
            sX[r * 65 + k] = (gr < n) ? X[gr * 64 + k] : 0.f;
        }
        __syncthreads();

        const int row = t >> 2;
        const int q   = t & 3;

        float4 a0 = {0,0,0,0}, a1 = {0,0,0,0}, a2 = {0,0,0,0}, a3 = {0,0,0,0};
        #pragma unroll 16
        for (int k = 0; k < 64; k++) {
            float x = sX[row * 65 + k];
            const float4* w4 = (const float4*)&sW[k * 64 + q * 16];
            float4 wa = w4[0], wb = w4[1], wc = w4[2], wd = w4[3];
            a0.x += x * wa.x; a0.y += x * wa.y; a0.z += x * wa.z; a0.w += x * wa.w;
            a1.x += x * wb.x; a1.y += x * wb.y; a1.z += x * wb.z; a1.w += x * wb.w;
            a2.x += x * wc.x; a2.y += x * wc.y; a2.z += x * wc.z; a2.w += x * wc.w;
            a3.x += x * wd.x; a3.y += x * wd.y; a3.z += x * wd.z; a3.w += x * wd.w;
        }
        int gr = r0 + row;
        if (gr < n) {
            float4* o = (float4*)&out[gr * 64 + q * 16];
            o[0] = a0; o[1] = a1; o[2] = a2; o[3] = a3;
        }
        return;
    }

    // ---- histogram part: 4 incidences per thread ----
    int b = blockIdx.x - gemm_blocks;
    int i = (b * 256 + threadIdx.x) * 4;
    if (i + 3 < nnz) {
        int4 v = *(const int4*)&vertex[i];
        int4 e = *(const int4*)&edges[i];
        atomicAdd(&g_ecnt[e.x], 1); atomicAdd(&g_ecnt[e.y], 1);
        atomicAdd(&g_ecnt[e.z], 1); atomicAdd(&g_ecnt[e.w], 1);
        atomicAdd(&g_vcnt[v.x], 1); atomicAdd(&g_vcnt[v.y], 1);
        atomicAdd(&g_vcnt[v.z], 1); atomicAdd(&g_vcnt[v.w], 1);
        atomicAdd(&g_att[v.x], homo[e.x]); atomicAdd(&g_att[v.y], homo[e.y]);
        atomicAdd(&g_att[v.z], homo[e.z]); atomicAdd(&g_att[v.w], homo[e.w]);
    } else {
        for (int k = i; k < nnz; k++) {
            int v = vertex[k], e = edges[k];
            atomicAdd(&g_ecnt[e], 1);
            atomicAdd(&g_vcnt[v], 1);
            atomicAdd(&g_att[v], homo[e]);
        }
    }
}

// ---------------- scan phase 1: per-tile partial sums ----------------
__global__ void scan_partial_kernel()
{
    const bool is_e = blockIdx.x < TE;
    const int  tile = is_e ? blockIdx.x : blockIdx.x - TE;
    const int  n    = is_e ? N_EDGES : N_NODES;
    const int* __restrict__ cnt = is_e ? g_ecnt : g_vcnt;
    int* __restrict__ part      = is_e ? g_epart : g_vpart;

    __shared__ int s_wsum[32];
    const int lane = threadIdx.x & 31;
    const int wid  = threadIdx.x >> 5;

    int base = tile * TILE + threadIdx.x * 4;
    int s = 0;
    #pragma unroll
    for (int k = 0; k < 4; k++) {
        int i = base + k;
        if (i < n) s += cnt[i];
    }
    #pragma unroll
    for (int o = 16; o; o >>= 1) s += __shfl_xor_sync(0xffffffffu, s, o);
    if (lane == 0) s_wsum[wid] = s;
    __syncthreads();
    if (wid == 0) {
        int w = s_wsum[lane];
        #pragma unroll
        for (int o = 16; o; o >>= 1) w += __shfl_xor_sync(0xffffffffu, w, o);
        if (lane == 0) part[tile] = w;
    }
}

// ---------------- scan phase 2: local scan + inline spine ----------------
__global__ void scan_final_kernel()
{
    const bool is_e = blockIdx.x < TE;
    const int  tile = is_e ? blockIdx.x : blockIdx.x - TE;
    const int  n    = is_e ? N_EDGES : N_NODES;
    const int  nt   = is_e ? TE : TV;
    const int* __restrict__ cnt = is_e ? g_ecnt : g_vcnt;
    const int* __restrict__ part= is_e ? g_epart : g_vpart;
    int* __restrict__ row       = is_e ? g_erow : g_vrow;
    int* __restrict__ off       = is_e ? g_eoff : g_voff;

    __shared__ int s_wsum[32];
    __shared__ int s_tile_off;
    const int lane = threadIdx.x & 31;
    const int wid  = threadIdx.x >> 5;

    if (wid == 0) {
        int p = (lane < nt) ? part[lane] : 0;
        int incl = p;
        #pragma unroll
        for (int o = 1; o < 32; o <<= 1) {
            int t = __shfl_up_sync(0xffffffffu, incl, o);
            if (lane >= o) incl += t;
        }
        if (lane == tile) s_tile_off = incl - p;
        if (tile == 0 && lane == nt - 1) row[n] = incl;
    }

    int base = tile * TILE + threadIdx.x * 4;
    int c[4];
    int s = 0;
    #pragma unroll
    for (int k = 0; k < 4; k++) {
        int i = base + k;
        c[k] = (i < n) ? cnt[i] : 0;
        s += c[k];
    }

    int v = s;
    #pragma unroll
    for (int o = 1; o < 32; o <<= 1) {
        int t = __shfl_up_sync(0xffffffffu, v, o);
        if (lane >= o) v += t;
    }
    if (lane == 31) s_wsum[wid] = v;
    __syncthreads();
    if (wid == 0) {
        int w = s_wsum[lane];
        int u = w;
        #pragma unroll
        for (int o = 1; o < 32; o <<= 1) {
            int t = __shfl_up_sync(0xffffffffu, u, o);
            if (lane >= o) u += t;
        }
        s_wsum[lane] = u - w;
    }
    __syncthreads();

    int excl = s_tile_off + s_wsum[wid] + (v - s);
    #pragma unroll
    for (int k = 0; k < 4; k++) {
        int i = base + k;
        if (i < n) { row[i] = excl; off[i] = excl; }
        excl += c[k];
    }
}

// ---------------- kernel: permutation scatter (4/thread, int4 loads) --------
__global__ void permute_kernel(const int* __restrict__ vertex,
                               const int* __restrict__ edges, int nnz)
{
    int i = (blockIdx.x * blockDim.x + threadIdx.x) * 4;
    if (i + 3 < nnz) {
        int4 v = *(const int4*)&vertex[i];
        int4 e = *(const int4*)&edges[i];
        g_evid[atomicAdd(&g_eoff[e.x], 1)] = v.x;
        g_evid[atomicAdd(&g_eoff[e.y], 1)] = v.y;
        g_evid[atomicAdd(&g_eoff[e.z], 1)] = v.z;
        g_evid[atomicAdd(&g_eoff[e.w], 1)] = v.w;
        g_veid[atomicAdd(&g_voff[v.x], 1)] = e.x;
        g_veid[atomicAdd(&g_voff[v.y], 1)] = e.y;
        g_veid[atomicAdd(&g_voff[v.z], 1)] = e.z;
        g_veid[atomicAdd(&g_voff[v.w], 1)] = e.w;
    } else {
        for (int k = i; k < nnz; k++) {
            int v = vertex[k], e = edges[k];
            g_evid[atomicAdd(&g_eoff[e], 1)] = v;
            g_veid[atomicAdd(&g_voff[v], 1)] = e;
        }
    }
}

// ---------------- kernel: edge aggregation (mean), warp/edge, 4 rows in flight
// quarter-warps: q = lane>>3 walks rows j = beg+q step 4; c = lane&7 owns 8 ch.
__global__ void edge_agg_kernel(const float* __restrict__ Xp)
{
    int e = (blockIdx.x * blockDim.x + threadIdx.x) >> 5;
    if (e >= N_EDGES) return;
    const int lane = threadIdx.x & 31;
    const int q = lane >> 3;
    const int c = lane & 7;

    int beg = g_erow[e], end = g_erow[e + 1];
    float4 a0 = {0,0,0,0}, a1 = {0,0,0,0};

    #pragma unroll 2
    for (int j = beg + q; j < end; j += 4) {
        int v = g_evid[j];
        const float4* p = (const float4*)&Xp[v * 64 + c * 8];
        float4 x0 = p[0], x1 = p[1];
        a0.x += x0.x; a0.y += x0.y; a0.z += x0.z; a0.w += x0.w;
        a1.x += x1.x; a1.y += x1.y; a1.z += x1.z; a1.w += x1.w;
    }
    // combine quarters (offsets 8 and 16)
    #pragma unroll
    for (int o = 8; o <= 16; o <<= 1) {
        a0.x += __shfl_xor_sync(0xffffffffu, a0.x, o);
        a0.y += __shfl_xor_sync(0xffffffffu, a0.y, o);
        a0.z += __shfl_xor_sync(0xffffffffu, a0.z, o);
        a0.w += __shfl_xor_sync(0xffffffffu, a0.w, o);
        a1.x += __shfl_xor_sync(0xffffffffu, a1.x, o);
        a1.y += __shfl_xor_sync(0xffffffffu, a1.y, o);
        a1.z += __shfl_xor_sync(0xffffffffu, a1.z, o);
        a1.w += __shfl_xor_sync(0xffffffffu, a1.w, o);
    }

    int deg = end - beg;
    float inv = (deg > 0) ? (1.f / (float)deg) : 0.f;
    if (q == 0) {
        float4* o = (float4*)&g_Xe[e * 64 + c * 8];
        float4 r0 = { a0.x*inv, a0.y*inv, a0.z*inv, a0.w*inv };
        float4 r1 = { a1.x*inv, a1.y*inv, a1.z*inv, a1.w*inv };
        o[0] = r0; o[1] = r1;
    }
}

// ---------------- kernel: node aggregation + residual + L2 norm -------------
__global__ void node_agg_kernel(float* __restrict__ out,
                                const float* __restrict__ homo, int n)
{
    int v = (blockIdx.x * blockDim.x + threadIdx.x) >> 5;
    if (v >= n) return;
    const int lane = threadIdx.x & 31;
    const int q = lane >> 3;
    const int c = lane & 7;

    int beg = g_vrow[v], end = g_vrow[v + 1];

    float wsum = g_att[v];
    float invw = (wsum > 0.f) ? (1.f / wsum) : 0.f;

    float4 a0 = {0,0,0,0}, a1 = {0,0,0,0};
    #pragma unroll 2
    for (int j = beg + q; j < end; j += 4) {
        int e = g_veid[j];
        float w = homo[e] * invw;
        const float4* p = (const float4*)&g_Xe[e * 64 + c * 8];
        float4 x0 = p[0], x1 = p[1];
        a0.x += w * x0.x; a0.y += w * x0.y; a0.z += w * x0.z; a0.w += w * x0.w;
        a1.x += w * x1.x; a1.y += w * x1.y; a1.z += w * x1.z; a1.w += w * x1.w;
    }
    #pragma unroll
    for (int o = 8; o <= 16; o <<= 1) {
        a0.x += __shfl_xor_sync(0xffffffffu, a0.x, o);
        a0.y += __shfl_xor_sync(0xffffffffu, a0.y, o);
        a0.z += __shfl_xor_sync(0xffffffffu, a0.z, o);
        a0.w += __shfl_xor_sync(0xffffffffu, a0.w, o);
        a1.x += __shfl_xor_sync(0xffffffffu, a1.x, o);
        a1.y += __shfl_xor_sync(0xffffffffu, a1.y, o);
        a1.z += __shfl_xor_sync(0xffffffffu, a1.z, o);
        a1.w += __shfl_xor_sync(0xffffffffu, a1.w, o);
    }

    // residual (Xp lives in out)
    const float4* rp = (const float4*)&out[v * 64 + c * 8];
    float4 r0 = rp[0], r1 = rp[1];
    a0.x += r0.x; a0.y += r0.y; a0.z += r0.z; a0.w += r0.w;
    a1.x += r1.x; a1.y += r1.y; a1.z += r1.z; a1.w += r1.w;

    // row-L2 norm: quarters hold identical sums; reduce across c (1,2,4)
    float s = a0.x*a0.x + a0.y*a0.y + a0.z*a0.z + a0.w*a0.w
            + a1.x*a1.x + a1.y*a1.y + a1.z*a1.z + a1.w*a1.w;
    #pragma unroll
    for (int o = 4; o; o >>= 1) s += __shfl_xor_sync(0xffffffffu, s, o);

    float norm  = sqrtf(s);
    float scale = (norm > 0.f) ? (1.f / fmaxf(norm, 1e-30f)) : 0.f;
    if (q == 0) {
        float4* o = (float4*)&out[v * 64 + c * 8];
        float4 w0 = { a0.x*scale, a0.y*scale, a0.z*scale, a0.w*scale };
        float4 w1 = { a1.x*scale, a1.y*scale, a1.z*scale, a1.w*scale };
        o[0] = w0; o[1] = w1;
    }
}

// ---------------- launch ----------------
extern "C" void kernel_launch(void* const* d_in, const int* in_sizes, int n_in,
                              void* d_out, int out_size)
{
    const float* X      = (const float*)d_in[0];
    const float* W      = (const float*)d_in[1];
    const float* homo   = (const float*)d_in[2];
    const int*   vertex = (const int*)  d_in[3];
    const int*   edges  = (const int*)  d_in[4];
    float*       out    = (float*)d_out;

    const int n   = in_sizes[0] / IN_CH;   // 100000
    const int nnz = in_sizes[3];           // 2000000

    zero_kernel<<<(N_NODES + 255) / 256, 256>>>();

    const int gemm_blocks = (n + 63) / 64;
    const int hist_blocks = (nnz + 1023) / 1024;
    gemm_hist_kernel<<<gemm_blocks + hist_blocks, 256>>>(
        X, W, out, homo, vertex, edges, n, nnz, gemm_blocks);

    scan_partial_kernel<<<TE + TV, 1024>>>();
    scan_final_kernel<<<TE + TV, 1024>>>();

    permute_kernel<<<(nnz / 4 + 255) / 256, 256>>>(vertex, edges, nnz);

    edge_agg_kernel<<<(N_EDGES * 32 + 255) / 256, 256>>>(out);
    node_agg_kernel<<<((long long)n * 32 + 255) / 256, 256>>>(out, homo, n);
}

// round 7
// speedup vs baseline: 1.0201x; 1.0201x over previous
#include <cuda_runtime.h>
#include <stdint.h>

#define N_NODES   100000
#define N_EDGES   25000
#define NNZ_MAX   2000000
#define HO        64
#define IN_CH     64

#define TILE      4096
#define TE        ((N_EDGES + TILE - 1) / TILE)   // 7
#define TV        ((N_NODES + TILE - 1) / TILE)   // 25

// ---------------- scratch (device globals; no allocation) ----------------
__device__ __align__(16) float g_Xe[N_EDGES * HO];
__device__ int   g_ecnt[N_EDGES];
__device__ int   g_vcnt[N_NODES];
__device__ float g_att[N_NODES];
__device__ int   g_erow[N_EDGES + 1];
__device__ int   g_vrow[N_NODES + 1];
__device__ int   g_eoff[N_EDGES];
__device__ int   g_voff[N_NODES];
__device__ int   g_evid[NNZ_MAX];
__device__ int   g_veid[NNZ_MAX];
__device__ int   g_epart[TE];
__device__ int   g_vpart[TV];

// ---------------- kernel A: zero counters ----------------
__global__ void zero_kernel()
{
    int idx = blockIdx.x * blockDim.x + threadIdx.x;
    if (idx < N_EDGES) g_ecnt[idx] = 0;
    if (idx < N_NODES) { g_vcnt[idx] = 0; g_att[idx] = 0.f; }
}

// ---------------- kernel B: fused GEMM (Xp = X@W -> out) + histograms -------
__global__ void gemm_hist_kernel(const float* __restrict__ X,
                                 const float* __restrict__ W,
                                 float* __restrict__ out,
                                 const float* __restrict__ homo,
                                 const int* __restrict__ vertex,
                                 const int* __restrict__ edges,
                                 int n, int nnz, int gemm_blocks)
{
    __shared__ float sW[64 * 64];
    __shared__ float sX[64 * 65];

    if (blockIdx.x < gemm_blocks) {
        const int t  = threadIdx.x;
        const int r0 = blockIdx.x * 64;

        #pragma unroll
        for (int idx = t; idx < 64 * 64; idx += 256) sW[idx] = W[idx];
        #pragma unroll
        for (int idx = t; idx < 64 * 64; idx += 256) {
            int r = idx >> 6, k = idx & 63;
            int gr = r0 + r;
            sX[r * 65 + k] = (gr < n) ? X[gr * 64 + k] : 0.f;
        }
        __syncthreads();

        const int row = t >> 2;
        const int q   = t & 3;

        float4 a0 = {0,0,0,0}, a1 = {0,0,0,0}, a2 = {0,0,0,0}, a3 = {0,0,0,0};
        #pragma unroll 16
        for (int k = 0; k < 64; k++) {
            float x = sX[row * 65 + k];
            const float4* w4 = (const float4*)&sW[k * 64 + q * 16];
            float4 wa = w4[0], wb = w4[1], wc = w4[2], wd = w4[3];
            a0.x += x * wa.x; a0.y += x * wa.y; a0.z += x * wa.z; a0.w += x * wa.w;
            a1.x += x * wb.x; a1.y += x * wb.y; a1.z += x * wb.z; a1.w += x * wb.w;
            a2.x += x * wc.x; a2.y += x * wc.y; a2.z += x * wc.z; a2.w += x * wc.w;
            a3.x += x * wd.x; a3.y += x * wd.y; a3.z += x * wd.z; a3.w += x * wd.w;
        }
        int gr = r0 + row;
        if (gr < n) {
            float4* o = (float4*)&out[gr * 64 + q * 16];
            o[0] = a0; o[1] = a1; o[2] = a2; o[3] = a3;
        }
        return;
    }

    // ---- histogram part: 4 incidences per thread ----
    int b = blockIdx.x - gemm_blocks;
    int i = (b * 256 + threadIdx.x) * 4;
    if (i + 3 < nnz) {
        int4 v = *(const int4*)&vertex[i];
        int4 e = *(const int4*)&edges[i];
        atomicAdd(&g_ecnt[e.x], 1); atomicAdd(&g_ecnt[e.y], 1);
        atomicAdd(&g_ecnt[e.z], 1); atomicAdd(&g_ecnt[e.w], 1);
        atomicAdd(&g_vcnt[v.x], 1); atomicAdd(&g_vcnt[v.y], 1);
        atomicAdd(&g_vcnt[v.z], 1); atomicAdd(&g_vcnt[v.w], 1);
        atomicAdd(&g_att[v.x], homo[e.x]); atomicAdd(&g_att[v.y], homo[e.y]);
        atomicAdd(&g_att[v.z], homo[e.z]); atomicAdd(&g_att[v.w], homo[e.w]);
    } else {
        for (int k = i; k < nnz; k++) {
            int v = vertex[k], e = edges[k];
            atomicAdd(&g_ecnt[e], 1);
            atomicAdd(&g_vcnt[v], 1);
            atomicAdd(&g_att[v], homo[e]);
        }
    }
}

// ---------------- scan phase 1: per-tile partial sums ----------------
__global__ void scan_partial_kernel()
{
    const bool is_e = blockIdx.x < TE;
    const int  tile = is_e ? blockIdx.x : blockIdx.x - TE;
    const int  n    = is_e ? N_EDGES : N_NODES;
    const int* __restrict__ cnt = is_e ? g_ecnt : g_vcnt;
    int* __restrict__ part      = is_e ? g_epart : g_vpart;

    __shared__ int s_wsum[32];
    const int lane = threadIdx.x & 31;
    const int wid  = threadIdx.x >> 5;

    int base = tile * TILE + threadIdx.x * 4;
    int s = 0;
    #pragma unroll
    for (int k = 0; k < 4; k++) {
        int i = base + k;
        if (i < n) s += cnt[i];
    }
    #pragma unroll
    for (int o = 16; o; o >>= 1) s += __shfl_xor_sync(0xffffffffu, s, o);
    if (lane == 0) s_wsum[wid] = s;
    __syncthreads();
    if (wid == 0) {
        int w = s_wsum[lane];
        #pragma unroll
        for (int o = 16; o; o >>= 1) w += __shfl_xor_sync(0xffffffffu, w, o);
        if (lane == 0) part[tile] = w;
    }
}

// ---------------- scan phase 2: local scan + inline spine ----------------
__global__ void scan_final_kernel()
{
    const bool is_e = blockIdx.x < TE;
    const int  tile = is_e ? blockIdx.x : blockIdx.x - TE;
    const int  n    = is_e ? N_EDGES : N_NODES;
    const int  nt   = is_e ? TE : TV;
    const int* __restrict__ cnt = is_e ? g_ecnt : g_vcnt;
    const int* __restrict__ part= is_e ? g_epart : g_vpart;
    int* __restrict__ row       = is_e ? g_erow : g_vrow;
    int* __restrict__ off       = is_e ? g_eoff : g_voff;

    __shared__ int s_wsum[32];
    __shared__ int s_tile_off;
    const int lane = threadIdx.x & 31;
    const int wid  = threadIdx.x >> 5;

    if (wid == 0) {
        int p = (lane < nt) ? part[lane] : 0;
        int incl = p;
        #pragma unroll
        for (int o = 1; o < 32; o <<= 1) {
            int t = __shfl_up_sync(0xffffffffu, incl, o);
            if (lane >= o) incl += t;
        }
        if (lane == tile) s_tile_off = incl - p;
        if (tile == 0 && lane == nt - 1) row[n] = incl;
    }

    int base = tile * TILE + threadIdx.x * 4;
    int c[4];
    int s = 0;
    #pragma unroll
    for (int k = 0; k < 4; k++) {
        int i = base + k;
        c[k] = (i < n) ? cnt[i] : 0;
        s += c[k];
    }

    int v = s;
    #pragma unroll
    for (int o = 1; o < 32; o <<= 1) {
        int t = __shfl_up_sync(0xffffffffu, v, o);
        if (lane >= o) v += t;
    }
    if (lane == 31) s_wsum[wid] = v;
    __syncthreads();
    if (wid == 0) {
        int w = s_wsum[lane];
        int u = w;
        #pragma unroll
        for (int o = 1; o < 32; o <<= 1) {
            int t = __shfl_up_sync(0xffffffffu, u, o);
            if (lane >= o) u += t;
        }
        s_wsum[lane] = u - w;
    }
    __syncthreads();

    int excl = s_tile_off + s_wsum[wid] + (v - s);
    #pragma unroll
    for (int k = 0; k < 4; k++) {
        int i = base + k;
        if (i < n) { row[i] = excl; off[i] = excl; }
        excl += c[k];
    }
}

// ---------------- kernel: permutation scatter (scalar, 1/thread) ------------
__global__ void permute_kernel(const int* __restrict__ vertex,
                               const int* __restrict__ edges, int nnz)
{
    int i = blockIdx.x * blockDim.x + threadIdx.x;
    if (i >= nnz) return;
    int v = vertex[i];
    int e = edges[i];
    int se = atomicAdd(&g_eoff[e], 1);
    g_evid[se] = v;
    int sv = atomicAdd(&g_voff[v], 1);
    g_veid[sv] = e;
}

// ---------------- kernel: edge aggregation (mean), warp/edge ----------------
// half-warps (16 lanes x float4 = 64ch), 4 independent accumulators -> 8 rows
// in flight per warp.
__global__ void edge_agg_kernel(const float* __restrict__ Xp)
{
    int e = (blockIdx.x * blockDim.x + threadIdx.x) >> 5;
    if (e >= N_EDGES) return;
    const int lane = threadIdx.x & 31;
    const int h = lane >> 4;
    const int c = lane & 15;

    int beg = g_erow[e], end = g_erow[e + 1];
    float4 a0 = {0,0,0,0}, a1 = {0,0,0,0}, a2 = {0,0,0,0}, a3 = {0,0,0,0};

    int j = beg + h;
    for (; j + 6 < end; j += 8) {
        int v0 = g_evid[j];
        int v1 = g_evid[j + 2];
        int v2 = g_evid[j + 4];
        int v3 = g_evid[j + 6];
        float4 x0 = *(const float4*)&Xp[v0 * 64 + c * 4];
        float4 x1 = *(const float4*)&Xp[v1 * 64 + c * 4];
        float4 x2 = *(const float4*)&Xp[v2 * 64 + c * 4];
        float4 x3 = *(const float4*)&Xp[v3 * 64 + c * 4];
        a0.x += x0.x; a0.y += x0.y; a0.z += x0.z; a0.w += x0.w;
        a1.x += x1.x; a1.y += x1.y; a1.z += x1.z; a1.w += x1.w;
        a2.x += x2.x; a2.y += x2.y; a2.z += x2.z; a2.w += x2.w;
        a3.x += x3.x; a3.y += x3.y; a3.z += x3.z; a3.w += x3.w;
    }
    for (; j < end; j += 2) {
        int v = g_evid[j];
        float4 x = *(const float4*)&Xp[v * 64 + c * 4];
        a0.x += x.x; a0.y += x.y; a0.z += x.z; a0.w += x.w;
    }
    a0.x += a1.x + a2.x + a3.x;
    a0.y += a1.y + a2.y + a3.y;
    a0.z += a1.z + a2.z + a3.z;
    a0.w += a1.w + a2.w + a3.w;

    a0.x += __shfl_xor_sync(0xffffffffu, a0.x, 16);
    a0.y += __shfl_xor_sync(0xffffffffu, a0.y, 16);
    a0.z += __shfl_xor_sync(0xffffffffu, a0.z, 16);
    a0.w += __shfl_xor_sync(0xffffffffu, a0.w, 16);

    int deg = end - beg;
    float inv = (deg > 0) ? (1.f / (float)deg) : 0.f;
    if (h == 0) {
        float4 r = { a0.x * inv, a0.y * inv, a0.z * inv, a0.w * inv };
        *(float4*)&g_Xe[e * 64 + c * 4] = r;
    }
}

// ---------------- kernel: node aggregation + residual + L2 norm -------------
__global__ void node_agg_kernel(float* __restrict__ out,
                                const float* __restrict__ homo, int n)
{
    int v = (blockIdx.x * blockDim.x + threadIdx.x) >> 5;
    if (v >= n) return;
    const int lane = threadIdx.x & 31;
    const int h = lane >> 4;
    const int c = lane & 15;

    int beg = g_vrow[v], end = g_vrow[v + 1];

    float wsum = g_att[v];
    float invw = (wsum > 0.f) ? (1.f / wsum) : 0.f;

    float4 a0 = {0,0,0,0}, a1 = {0,0,0,0}, a2 = {0,0,0,0}, a3 = {0,0,0,0};

    int j = beg + h;
    for (; j + 6 < end; j += 8) {
        int e0 = g_veid[j];
        int e1 = g_veid[j + 2];
        int e2 = g_veid[j + 4];
        int e3 = g_veid[j + 6];
        float w0 = homo[e0] * invw;
        float w1 = homo[e1] * invw;
        float w2 = homo[e2] * invw;
        float w3 = homo[e3] * invw;
        float4 x0 = *(const float4*)&g_Xe[e0 * 64 + c * 4];
        float4 x1 = *(const float4*)&g_Xe[e1 * 64 + c * 4];
        float4 x2 = *(const float4*)&g_Xe[e2 * 64 + c * 4];
        float4 x3 = *(const float4*)&g_Xe[e3 * 64 + c * 4];
        a0.x += w0 * x0.x; a0.y += w0 * x0.y; a0.z += w0 * x0.z; a0.w += w0 * x0.w;
        a1.x += w1 * x1.x; a1.y += w1 * x1.y; a1.z += w1 * x1.z; a1.w += w1 * x1.w;
        a2.x += w2 * x2.x; a2.y += w2 * x2.y; a2.z += w2 * x2.z; a2.w += w2 * x2.w;
        a3.x += w3 * x3.x; a3.y += w3 * x3.y; a3.z += w3 * x3.z; a3.w += w3 * x3.w;
    }
    for (; j < end; j += 2) {
        int e = g_veid[j];
        float w = homo[e] * invw;
        float4 x = *(const float4*)&g_Xe[e * 64 + c * 4];
        a0.x += w * x.x; a0.y += w * x.y; a0.z += w * x.z; a0.w += w * x.w;
    }
    a0.x += a1.x + a2.x + a3.x;
    a0.y += a1.y + a2.y + a3.y;
    a0.z += a1.z + a2.z + a3.z;
    a0.w += a1.w + a2.w + a3.w;

    a0.x += __shfl_xor_sync(0xffffffffu, a0.x, 16);
    a0.y += __shfl_xor_sync(0xffffffffu, a0.y, 16);
    a0.z += __shfl_xor_sync(0xffffffffu, a0.z, 16);
    a0.w += __shfl_xor_sync(0xffffffffu, a0.w, 16);

    // residual (Xp lives in out)
    float4 r = *(const float4*)&out[v * 64 + c * 4];
    a0.x += r.x; a0.y += r.y; a0.z += r.z; a0.w += r.w;

    // row-L2 norm: halves identical; butterfly within half (offsets 1..8)
    float s = a0.x * a0.x + a0.y * a0.y + a0.z * a0.z + a0.w * a0.w;
    #pragma unroll
    for (int o = 8; o; o >>= 1) s += __shfl_xor_sync(0xffffffffu, s, o);

    float norm  = sqrtf(s);
    float scale = (norm > 0.f) ? (1.f / fmaxf(norm, 1e-30f)) : 0.f;
    if (h == 0) {
        float4 w = { a0.x * scale, a0.y * scale, a0.z * scale, a0.w * scale };
        *(float4*)&out[v * 64 + c * 4] = w;
    }
}

// ---------------- launch ----------------
extern "C" void kernel_launch(void* const* d_in, const int* in_sizes, int n_in,
                              void* d_out, int out_size)
{
    const float* X      = (const float*)d_in[0];
    const float* W      = (const float*)d_in[1];
    const float* homo   = (const float*)d_in[2];
    const int*   vertex = (const int*)  d_in[3];
    const int*   edges  = (const int*)  d_in[4];
    float*       out    = (float*)d_out;

    const int n   = in_sizes[0] / IN_CH;   // 100000
    const int nnz = in_sizes[3];           // 2000000

    zero_kernel<<<(N_NODES + 255) / 256, 256>>>();

    const int gemm_blocks = (n + 63) / 64;
    const int hist_blocks = (nnz + 1023) / 1024;
    gemm_hist_kernel<<<gemm_blocks + hist_blocks, 256>>>(
        X, W, out, homo, vertex, edges, n, nnz, gemm_blocks);

    scan_partial_kernel<<<TE + TV, 1024>>>();
    scan_final_kernel<<<TE + TV, 1024>>>();

    permute_kernel<<<(nnz + 255) / 256, 256>>>(vertex, edges, nnz);

    edge_agg_kernel<<<(N_EDGES * 32 + 255) / 256, 256>>>(out);
    node_agg_kernel<<<((long long)n * 32 + 255) / 256, 256>>>(out, homo, n);
}

// round 8
// speedup vs baseline: 1.0728x; 1.0516x over previous
#include <cuda_runtime.h>
#include <stdint.h>

#define N_NODES   100000
#define N_EDGES   25000
#define NNZ_MAX   2000000
#define HO        64
#define IN_CH     64

#define TILE      4096
#define TE        ((N_EDGES + TILE - 1) / TILE)   // 7
#define TV        ((N_NODES + TILE - 1) / TILE)   // 25
#define NTILES    (TE + TV)                        // 32

// ---------------- scratch (device globals; no allocation) ----------------
__device__ __align__(16) float g_Xe[N_EDGES * HO];
__device__ int   g_ecnt[N_EDGES];
__device__ int   g_vcnt[N_NODES];
__device__ float g_att[N_NODES];
__device__ int   g_erow[N_EDGES + 1];
__device__ int   g_vrow[N_NODES + 1];
__device__ int   g_eoff[N_EDGES];
__device__ int   g_voff[N_NODES];
__device__ int   g_evid[NNZ_MAX];
__device__ int   g_veid[NNZ_MAX];
__device__ int   g_epart[TE];
__device__ int   g_vpart[TV];
__device__ int   g_scan_arrive;

// ---------------- kernel A: zero counters + barrier flag ----------------
__global__ void zero_kernel()
{
    int idx = blockIdx.x * blockDim.x + threadIdx.x;
    if (idx == 0) g_scan_arrive = 0;
    if (idx < N_EDGES) g_ecnt[idx] = 0;
    if (idx < N_NODES) { g_vcnt[idx] = 0; g_att[idx] = 0.f; }
}

// ---------------- kernel B: histograms (4 incidences / thread) ----------
__global__ void hist_kernel(const float* __restrict__ homo,
                            const int* __restrict__ vertex,
                            const int* __restrict__ edges, int nnz)
{
    int i = (blockIdx.x * blockDim.x + threadIdx.x) * 4;
    if (i + 3 < nnz) {
        int4 v = *(const int4*)&vertex[i];
        int4 e = *(const int4*)&edges[i];
        atomicAdd(&g_ecnt[e.x], 1); atomicAdd(&g_ecnt[e.y], 1);
        atomicAdd(&g_ecnt[e.z], 1); atomicAdd(&g_ecnt[e.w], 1);
        atomicAdd(&g_vcnt[v.x], 1); atomicAdd(&g_vcnt[v.y], 1);
        atomicAdd(&g_vcnt[v.z], 1); atomicAdd(&g_vcnt[v.w], 1);
        atomicAdd(&g_att[v.x], homo[e.x]); atomicAdd(&g_att[v.y], homo[e.y]);
        atomicAdd(&g_att[v.z], homo[e.z]); atomicAdd(&g_att[v.w], homo[e.w]);
    } else {
        for (int k = i; k < nnz; k++) {
            int v = vertex[k], e = edges[k];
            atomicAdd(&g_ecnt[e], 1);
            atomicAdd(&g_vcnt[v], 1);
            atomicAdd(&g_att[v], homo[e]);
        }
    }
}

// ---------------- kernel C: fused scan (32 blocks, soft global barrier) -----
// Blocks [0,TE): edge tiles; [TE,NTILES): vertex tiles. All 32 blocks are
// guaranteed co-resident (148 SMs), so the arrive-and-spin barrier is safe.
__global__ void scan_kernel()
{
    const bool is_e = blockIdx.x < TE;
    const int  tile = is_e ? blockIdx.x : blockIdx.x - TE;
    const int  n    = is_e ? N_EDGES : N_NODES;
    const int  nt   = is_e ? TE : TV;
    const int* __restrict__ cnt  = is_e ? g_ecnt : g_vcnt;
    int* __restrict__ part       = is_e ? g_epart : g_vpart;
    int* __restrict__ row        = is_e ? g_erow : g_vrow;
    int* __restrict__ off        = is_e ? g_eoff : g_voff;

    __shared__ int s_wsum[32];
    __shared__ int s_tile_off;
    const int lane = threadIdx.x & 31;
    const int wid  = threadIdx.x >> 5;

    // phase 1: local counts + warp scan + block total
    int base = tile * TILE + threadIdx.x * 4;
    int c[4];
    int s = 0;
    #pragma unroll
    for (int k = 0; k < 4; k++) {
        int i = base + k;
        c[k] = (i < n) ? cnt[i] : 0;
        s += c[k];
    }
    int v = s;
    #pragma unroll
    for (int o = 1; o < 32; o <<= 1) {
        int t = __shfl_up_sync(0xffffffffu, v, o);
        if (lane >= o) v += t;
    }
    if (lane == 31) s_wsum[wid] = v;
    __syncthreads();

    if (wid == 0) {
        int w = s_wsum[lane];
        int tot = w;
        #pragma unroll
        for (int o = 16; o; o >>= 1) tot += __shfl_xor_sync(0xffffffffu, tot, o);
        if (lane == 0) {
            part[tile] = tot;
            __threadfence();
            atomicAdd(&g_scan_arrive, 1);
        }
    }
    // soft global barrier
    if (threadIdx.x == 0) {
        while (atomicAdd(&g_scan_arrive, 0) < NTILES) { }
    }
    __syncthreads();
    __threadfence();

    // phase 2: spine scan (warp 0) + exclusive warp offsets
    if (wid == 0) {
        const int* p_arr = is_e ? g_epart : g_vpart;
        int p = (lane < nt) ? p_arr[lane] : 0;
        int incl = p;
        #pragma unroll
        for (int o = 1; o < 32; o <<= 1) {
            int t = __shfl_up_sync(0xffffffffu, incl, o);
            if (lane >= o) incl += t;
        }
        if (lane == tile) s_tile_off = incl - p;
        if (tile == 0 && lane == nt - 1) row[n] = incl;

        // exclusive scan of warp sums (in-place)
        int w = s_wsum[lane];
        int u = w;
        #pragma unroll
        for (int o = 1; o < 32; o <<= 1) {
            int t = __shfl_up_sync(0xffffffffu, u, o);
            if (lane >= o) u += t;
        }
        s_wsum[lane] = u - w;
    }
    __syncthreads();

    int excl = s_tile_off + s_wsum[wid] + (v - s);
    #pragma unroll
    for (int k = 0; k < 4; k++) {
        int i = base + k;
        if (i < n) { row[i] = excl; off[i] = excl; }
        excl += c[k];
    }
}

// ---------------- kernel D: fused GEMM (Xp = X@W) + permutation scatter -----
// blocks [0, gemm_blocks): gemm; rest: permute (scalar, 1 incidence/thread).
__global__ void gemm_perm_kernel(const float* __restrict__ X,
                                 const float* __restrict__ W,
                                 float* __restrict__ out,
                                 const int* __restrict__ vertex,
                                 const int* __restrict__ edges,
                                 int n, int nnz, int gemm_blocks)
{
    __shared__ float sW[64 * 64];
    __shared__ float sX[64 * 65];

    if (blockIdx.x < gemm_blocks) {
        const int t  = threadIdx.x;
        const int r0 = blockIdx.x * 64;

        #pragma unroll
        for (int idx = t; idx < 64 * 64; idx += 256) sW[idx] = W[idx];
        #pragma unroll
        for (int idx = t; idx < 64 * 64; idx += 256) {
            int r = idx >> 6, k = idx & 63;
            int gr = r0 + r;
            sX[r * 65 + k] = (gr < n) ? X[gr * 64 + k] : 0.f;
        }
        __syncthreads();

        const int row = t >> 2;
        const int q   = t & 3;

        float4 a0 = {0,0,0,0}, a1 = {0,0,0,0}, a2 = {0,0,0,0}, a3 = {0,0,0,0};
        #pragma unroll 16
        for (int k = 0; k < 64; k++) {
            float x = sX[row * 65 + k];
            const float4* w4 = (const float4*)&sW[k * 64 + q * 16];
            float4 wa = w4[0], wb = w4[1], wc = w4[2], wd = w4[3];
            a0.x += x * wa.x; a0.y += x * wa.y; a0.z += x * wa.z; a0.w += x * wa.w;
            a1.x += x * wb.x; a1.y += x * wb.y; a1.z += x * wb.z; a1.w += x * wb.w;
            a2.x += x * wc.x; a2.y += x * wc.y; a2.z += x * wc.z; a2.w += x * wc.w;
            a3.x += x * wd.x; a3.y += x * wd.y; a3.z += x * wd.z; a3.w += x * wd.w;
        }
        int gr = r0 + row;
        if (gr < n) {
            float4* o = (float4*)&out[gr * 64 + q * 16];
            o[0] = a0; o[1] = a1; o[2] = a2; o[3] = a3;
        }
        return;
    }

    int i = (blockIdx.x - gemm_blocks) * 256 + threadIdx.x;
    if (i >= nnz) return;
    int v = vertex[i];
    int e = edges[i];
    int se = atomicAdd(&g_eoff[e], 1);
    g_evid[se] = v;
    int sv = atomicAdd(&g_voff[v], 1);
    g_veid[sv] = e;
}

// ---------------- kernel E: edge aggregation (mean), warp/edge --------------
// half-warps (16 lanes x float4 = 64 ch), unroll-2 (round-4 proven shape)
__global__ void edge_agg_kernel(const float* __restrict__ Xp)
{
    int e = (blockIdx.x * blockDim.x + threadIdx.x) >> 5;
    if (e >= N_EDGES) return;
    const int lane = threadIdx.x & 31;
    const int h = lane >> 4;
    const int c = lane & 15;

    int beg = g_erow[e], end = g_erow[e + 1];
    float4 acc = {0.f, 0.f, 0.f, 0.f};

    #pragma unroll 2
    for (int j = beg + h; j < end; j += 2) {
        int v = g_evid[j];
        float4 x = *(const float4*)&Xp[v * 64 + c * 4];
        acc.x += x.x; acc.y += x.y; acc.z += x.z; acc.w += x.w;
    }
    acc.x += __shfl_xor_sync(0xffffffffu, acc.x, 16);
    acc.y += __shfl_xor_sync(0xffffffffu, acc.y, 16);
    acc.z += __shfl_xor_sync(0xffffffffu, acc.z, 16);
    acc.w += __shfl_xor_sync(0xffffffffu, acc.w, 16);

    int deg = end - beg;
    float inv = (deg > 0) ? (1.f / (float)deg) : 0.f;
    if (h == 0) {
        float4 r = { acc.x * inv, acc.y * inv, acc.z * inv, acc.w * inv };
        *(float4*)&g_Xe[e * 64 + c * 4] = r;
    }
}

// ---------------- kernel F: node aggregation + residual + L2 norm -----------
__global__ void node_agg_kernel(float* __restrict__ out,
                                const float* __restrict__ homo, int n)
{
    int v = (blockIdx.x * blockDim.x + threadIdx.x) >> 5;
    if (v >= n) return;
    const int lane = threadIdx.x & 31;
    const int h = lane >> 4;
    const int c = lane & 15;

    int beg = g_vrow[v], end = g_vrow[v + 1];

    float wsum = g_att[v];
    float invw = (wsum > 0.f) ? (1.f / wsum) : 0.f;

    float4 acc = {0.f, 0.f, 0.f, 0.f};
    #pragma unroll 2
    for (int j = beg + h; j < end; j += 2) {
        int e = g_veid[j];
        float w = homo[e] * invw;
        float4 xe = *(const float4*)&g_Xe[e * 64 + c * 4];
        acc.x += w * xe.x; acc.y += w * xe.y;
        acc.z += w * xe.z; acc.w += w * xe.w;
    }
    acc.x += __shfl_xor_sync(0xffffffffu, acc.x, 16);
    acc.y += __shfl_xor_sync(0xffffffffu, acc.y, 16);
    acc.z += __shfl_xor_sync(0xffffffffu, acc.z, 16);
    acc.w += __shfl_xor_sync(0xffffffffu, acc.w, 16);

    // residual (Xp lives in out)
    float4 r = *(const float4*)&out[v * 64 + c * 4];
    acc.x += r.x; acc.y += r.y; acc.z += r.z; acc.w += r.w;

    // row-L2 norm: halves identical; butterfly within half
    float s = acc.x * acc.x + acc.y * acc.y + acc.z * acc.z + acc.w * acc.w;
    #pragma unroll
    for (int o = 8; o; o >>= 1) s += __shfl_xor_sync(0xffffffffu, s, o);

    float norm  = sqrtf(s);
    float scale = (norm > 0.f) ? (1.f / fmaxf(norm, 1e-30f)) : 0.f;
    if (h == 0) {
        float4 w = { acc.x * scale, acc.y * scale, acc.z * scale, acc.w * scale };
        *(float4*)&out[v * 64 + c * 4] = w;
    }
}

// ---------------- launch ----------------
extern "C" void kernel_launch(void* const* d_in, const int* in_sizes, int n_in,
                              void* d_out, int out_size)
{
    const float* X      = (const float*)d_in[0];
    const float* W      = (const float*)d_in[1];
    const float* homo   = (const float*)d_in[2];
    const int*   vertex = (const int*)  d_in[3];
    const int*   edges  = (const int*)  d_in[4];
    float*       out    = (float*)d_out;

    const int n   = in_sizes[0] / IN_CH;   // 100000
    const int nnz = in_sizes[3];           // 2000000

    zero_kernel<<<(N_NODES + 255) / 256, 256>>>();

    hist_kernel<<<(nnz / 4 + 255) / 256, 256>>>(homo, vertex, edges, nnz);

    scan_kernel<<<NTILES, 1024>>>();

    const int gemm_blocks = (n + 63) / 64;
    const int perm_blocks = (nnz + 255) / 256;
    gemm_perm_kernel<<<gemm_blocks + perm_blocks, 256>>>(
        X, W, out, vertex, edges, n, nnz, gemm_blocks);

    edge_agg_kernel<<<(N_EDGES * 32 + 255) / 256, 256>>>(out);
    node_agg_kernel<<<((long long)n * 32 + 255) / 256, 256>>>(out, homo, n);
}

// round 9
// speedup vs baseline: 1.0971x; 1.0227x over previous
#include <cuda_runtime.h>
#include <stdint.h>

#define N_NODES   100000
#define N_EDGES   25000
#define NNZ_MAX   2000000
#define HO        64
#define IN_CH     64

#define TILE      4096
#define TE        ((N_EDGES + TILE - 1) / TILE)   // 7
#define TV        ((N_NODES + TILE - 1) / TILE)   // 25
#define NTILES    (TE + TV)                        // 32

// ---------------- scratch (device globals; no allocation) ----------------
__device__ __align__(16) float g_Xe[N_EDGES * HO];
__device__ int   g_ecnt[N_EDGES];
__device__ int   g_vcnt[N_NODES];
__device__ float g_att[N_NODES];
__device__ int   g_erow[N_EDGES + 1];
__device__ int   g_vrow[N_NODES + 1];
__device__ int   g_eoff[N_EDGES];
__device__ int   g_voff[N_NODES];
__device__ int   g_evid[NNZ_MAX];
__device__ int   g_veid[NNZ_MAX];
__device__ int   g_epart[TE];
__device__ int   g_vpart[TV];
__device__ int   g_scan_arrive;

// ---------------- kernel A: zero counters + barrier flag ----------------
__global__ void zero_kernel()
{
    int idx = blockIdx.x * blockDim.x + threadIdx.x;
    if (idx == 0) g_scan_arrive = 0;
    if (idx < N_EDGES) g_ecnt[idx] = 0;
    if (idx < N_NODES) { g_vcnt[idx] = 0; g_att[idx] = 0.f; }
}

// ---------------- kernel B: fused GEMM (Xp = X@W -> out) + histograms -------
__global__ void gemm_hist_kernel(const float* __restrict__ X,
                                 const float* __restrict__ W,
                                 float* __restrict__ out,
                                 const float* __restrict__ homo,
                                 const int* __restrict__ vertex,
                                 const int* __restrict__ edges,
                                 int n, int nnz, int gemm_blocks)
{
    __shared__ float sW[64 * 64];
    __shared__ float sX[64 * 65];

    if (blockIdx.x < gemm_blocks) {
        const int t  = threadIdx.x;
        const int r0 = blockIdx.x * 64;

        #pragma unroll
        for (int idx = t; idx < 64 * 64; idx += 256) sW[idx] = W[idx];
        #pragma unroll
        for (int idx = t; idx < 64 * 64; idx += 256) {
            int r = idx >> 6, k = idx & 63;
            int gr = r0 + r;
            sX[r * 65 + k] = (gr < n) ? X[gr * 64 + k] : 0.f;
        }
        __syncthreads();

        const int row = t >> 2;
        const int q   = t & 3;

        float4 a0 = {0,0,0,0}, a1 = {0,0,0,0}, a2 = {0,0,0,0}, a3 = {0,0,0,0};
        #pragma unroll 16
        for (int k = 0; k < 64; k++) {
            float x = sX[row * 65 + k];
            const float4* w4 = (const float4*)&sW[k * 64 + q * 16];
            float4 wa = w4[0], wb = w4[1], wc = w4[2], wd = w4[3];
            a0.x += x * wa.x; a0.y += x * wa.y; a0.z += x * wa.z; a0.w += x * wa.w;
            a1.x += x * wb.x; a1.y += x * wb.y; a1.z += x * wb.z; a1.w += x * wb.w;
            a2.x += x * wc.x; a2.y += x * wc.y; a2.z += x * wc.z; a2.w += x * wc.w;
            a3.x += x * wd.x; a3.y += x * wd.y; a3.z += x * wd.z; a3.w += x * wd.w;
        }
        int gr = r0 + row;
        if (gr < n) {
            float4* o = (float4*)&out[gr * 64 + q * 16];
            o[0] = a0; o[1] = a1; o[2] = a2; o[3] = a3;
        }
        return;
    }

    // ---- histogram part: 4 incidences per thread ----
    int b = blockIdx.x - gemm_blocks;
    int i = (b * 256 + threadIdx.x) * 4;
    if (i + 3 < nnz) {
        int4 v = *(const int4*)&vertex[i];
        int4 e = *(const int4*)&edges[i];
        atomicAdd(&g_ecnt[e.x], 1); atomicAdd(&g_ecnt[e.y], 1);
        atomicAdd(&g_ecnt[e.z], 1); atomicAdd(&g_ecnt[e.w], 1);
        atomicAdd(&g_vcnt[v.x], 1); atomicAdd(&g_vcnt[v.y], 1);
        atomicAdd(&g_vcnt[v.z], 1); atomicAdd(&g_vcnt[v.w], 1);
        atomicAdd(&g_att[v.x], homo[e.x]); atomicAdd(&g_att[v.y], homo[e.y]);
        atomicAdd(&g_att[v.z], homo[e.z]); atomicAdd(&g_att[v.w], homo[e.w]);
    } else {
        for (int k = i; k < nnz; k++) {
            int v = vertex[k], e = edges[k];
            atomicAdd(&g_ecnt[e], 1);
            atomicAdd(&g_vcnt[v], 1);
            atomicAdd(&g_att[v], homo[e]);
        }
    }
}

// ---------------- kernel C: fused scan (32 blocks, soft global barrier) -----
__global__ void scan_kernel()
{
    const bool is_e = blockIdx.x < TE;
    const int  tile = is_e ? blockIdx.x : blockIdx.x - TE;
    const int  n    = is_e ? N_EDGES : N_NODES;
    const int  nt   = is_e ? TE : TV;
    const int* __restrict__ cnt  = is_e ? g_ecnt : g_vcnt;
    int* __restrict__ part       = is_e ? g_epart : g_vpart;
    int* __restrict__ row        = is_e ? g_erow : g_vrow;
    int* __restrict__ off        = is_e ? g_eoff : g_voff;

    __shared__ int s_wsum[32];
    __shared__ int s_tile_off;
    const int lane = threadIdx.x & 31;
    const int wid  = threadIdx.x >> 5;

    int base = tile * TILE + threadIdx.x * 4;
    int c[4];
    int s = 0;
    #pragma unroll
    for (int k = 0; k < 4; k++) {
        int i = base + k;
        c[k] = (i < n) ? cnt[i] : 0;
        s += c[k];
    }
    int v = s;
    #pragma unroll
    for (int o = 1; o < 32; o <<= 1) {
        int t = __shfl_up_sync(0xffffffffu, v, o);
        if (lane >= o) v += t;
    }
    if (lane == 31) s_wsum[wid] = v;
    __syncthreads();

    if (wid == 0) {
        int w = s_wsum[lane];
        int tot = w;
        #pragma unroll
        for (int o = 16; o; o >>= 1) tot += __shfl_xor_sync(0xffffffffu, tot, o);
        if (lane == 0) {
            part[tile] = tot;
            __threadfence();
            atomicAdd(&g_scan_arrive, 1);
        }
    }
    if (threadIdx.x == 0) {
        while (atomicAdd(&g_scan_arrive, 0) < NTILES) { }
    }
    __syncthreads();
    __threadfence();

    if (wid == 0) {
        const int* p_arr = is_e ? g_epart : g_vpart;
        int p = (lane < nt) ? p_arr[lane] : 0;
        int incl = p;
        #pragma unroll
        for (int o = 1; o < 32; o <<= 1) {
            int t = __shfl_up_sync(0xffffffffu, incl, o);
            if (lane >= o) incl += t;
        }
        if (lane == tile) s_tile_off = incl - p;
        if (tile == 0 && lane == nt - 1) row[n] = incl;

        int w = s_wsum[lane];
        int u = w;
        #pragma unroll
        for (int o = 1; o < 32; o <<= 1) {
            int t = __shfl_up_sync(0xffffffffu, u, o);
            if (lane >= o) u += t;
        }
        s_wsum[lane] = u - w;
    }
    __syncthreads();

    int excl = s_tile_off + s_wsum[wid] + (v - s);
    #pragma unroll
    for (int k = 0; k < 4; k++) {
        int i = base + k;
        if (i < n) { row[i] = excl; off[i] = excl; }
        excl += c[k];
    }
}

// ---------------- kernel D: edge-side permutation (g_evid only) -------------
__global__ void permE_kernel(const int* __restrict__ vertex,
                             const int* __restrict__ edges, int nnz)
{
    int i = blockIdx.x * blockDim.x + threadIdx.x;
    if (i >= nnz) return;
    int v = vertex[i];
    int e = edges[i];
    g_evid[atomicAdd(&g_eoff[e], 1)] = v;
}

// ---------------- kernel E: fused edge_agg + vertex-side permutation --------
// blocks [0, agg_blocks): edge aggregation (mean); rest: permV (g_veid).
__global__ void edgeagg_permV_kernel(const float* __restrict__ Xp,
                                     const int* __restrict__ vertex,
                                     const int* __restrict__ edges,
                                     int nnz, int agg_blocks)
{
    if (blockIdx.x < agg_blocks) {
        int e = (blockIdx.x * blockDim.x + threadIdx.x) >> 5;
        if (e >= N_EDGES) return;
        const int lane = threadIdx.x & 31;
        const int h = lane >> 4;
        const int c = lane & 15;

        int beg = g_erow[e], end = g_erow[e + 1];
        float4 acc = {0.f, 0.f, 0.f, 0.f};

        #pragma unroll 2
        for (int j = beg + h; j < end; j += 2) {
            int v = g_evid[j];
            float4 x = *(const float4*)&Xp[v * 64 + c * 4];
            acc.x += x.x; acc.y += x.y; acc.z += x.z; acc.w += x.w;
        }
        acc.x += __shfl_xor_sync(0xffffffffu, acc.x, 16);
        acc.y += __shfl_xor_sync(0xffffffffu, acc.y, 16);
        acc.z += __shfl_xor_sync(0xffffffffu, acc.z, 16);
        acc.w += __shfl_xor_sync(0xffffffffu, acc.w, 16);

        int deg = end - beg;
        float inv = (deg > 0) ? (1.f / (float)deg) : 0.f;
        if (h == 0) {
            float4 r = { acc.x * inv, acc.y * inv, acc.z * inv, acc.w * inv };
            *(float4*)&g_Xe[e * 64 + c * 4] = r;
        }
        return;
    }

    int i = (blockIdx.x - agg_blocks) * 256 + threadIdx.x;
    if (i >= nnz) return;
    int v = vertex[i];
    int e = edges[i];
    g_veid[atomicAdd(&g_voff[v], 1)] = e;
}

// ---------------- kernel F: node aggregation + residual + L2 norm -----------
__global__ void node_agg_kernel(float* __restrict__ out,
                                const float* __restrict__ homo, int n)
{
    int v = (blockIdx.x * blockDim.x + threadIdx.x) >> 5;
    if (v >= n) return;
    const int lane = threadIdx.x & 31;
    const int h = lane >> 4;
    const int c = lane & 15;

    int beg = g_vrow[v], end = g_vrow[v + 1];

    float wsum = g_att[v];
    float invw = (wsum > 0.f) ? (1.f / wsum) : 0.f;

    float4 acc = {0.f, 0.f, 0.f, 0.f};
    #pragma unroll 2
    for (int j = beg + h; j < end; j += 2) {
        int e = g_veid[j];
        float w = homo[e] * invw;
        float4 xe = *(const float4*)&g_Xe[e * 64 + c * 4];
        acc.x += w * xe.x; acc.y += w * xe.y;
        acc.z += w * xe.z; acc.w += w * xe.w;
    }
    acc.x += __shfl_xor_sync(0xffffffffu, acc.x, 16);
    acc.y += __shfl_xor_sync(0xffffffffu, acc.y, 16);
    acc.z += __shfl_xor_sync(0xffffffffu, acc.z, 16);
    acc.w += __shfl_xor_sync(0xffffffffu, acc.w, 16);

    float4 r = *(const float4*)&out[v * 64 + c * 4];
    acc.x += r.x; acc.y += r.y; acc.z += r.z; acc.w += r.w;

    float s = acc.x * acc.x + acc.y * acc.y + acc.z * acc.z + acc.w * acc.w;
    #pragma unroll
    for (int o = 8; o; o >>= 1) s += __shfl_xor_sync(0xffffffffu, s, o);

    float norm  = sqrtf(s);
    float scale = (norm > 0.f) ? (1.f / fmaxf(norm, 1e-30f)) : 0.f;
    if (h == 0) {
        float4 w = { acc.x * scale, acc.y * scale, acc.z * scale, acc.w * scale };
        *(float4*)&out[v * 64 + c * 4] = w;
    }
}

// ---------------- launch ----------------
extern "C" void kernel_launch(void* const* d_in, const int* in_sizes, int n_in,
                              void* d_out, int out_size)
{
    const float* X      = (const float*)d_in[0];
    const float* W      = (const float*)d_in[1];
    const float* homo   = (const float*)d_in[2];
    const int*   vertex = (const int*)  d_in[3];
    const int*   edges  = (const int*)  d_in[4];
    float*       out    = (float*)d_out;

    const int n   = in_sizes[0] / IN_CH;   // 100000
    const int nnz = in_sizes[3];           // 2000000

    zero_kernel<<<(N_NODES + 255) / 256, 256>>>();

    const int gemm_blocks = (n + 63) / 64;
    const int hist_blocks = (nnz + 1023) / 1024;
    gemm_hist_kernel<<<gemm_blocks + hist_blocks, 256>>>(
        X, W, out, homo, vertex, edges, n, nnz, gemm_blocks);

    scan_kernel<<<NTILES, 1024>>>();

    permE_kernel<<<(nnz + 255) / 256, 256>>>(vertex, edges, nnz);

    const int agg_blocks  = (N_EDGES * 32 + 255) / 256;
    const int perm_blocks = (nnz + 255) / 256;
    edgeagg_permV_kernel<<<agg_blocks + perm_blocks, 256>>>(
        out, vertex, edges, nnz, agg_blocks);

    node_agg_kernel<<<((long long)n * 32 + 255) / 256, 256>>>(out, homo, n);
}